// round 1
// baseline (speedup 1.0000x reference)
#include <cuda_runtime.h>
#include <cuda_bf16.h>

#define N_GENE 4762
#define N_CELL 847
#define D 256
#define E_MAX 200064

// ---------------- device scratch (no allocations allowed) ----------------
__device__ int   g_deg_gsrc[N_GENE];     // g2c: out-degree of genes
__device__ int   g_deg_cdst[N_CELL];     // g2c: in-degree of cells
__device__ int   g_deg_csrc[N_CELL];     // c2g: out-degree of cells
__device__ int   g_deg_gdst[N_GENE];     // c2g: in-degree of genes
__device__ int   g_offs_c[N_CELL + 1];   // CSR offsets, g2c grouped by cell dst
__device__ int   g_offs_g[N_GENE + 1];   // CSR offsets, c2g grouped by gene dst
__device__ int   g_cursor_c[N_CELL];
__device__ int   g_cursor_g[N_GENE];
__device__ int   g_csr_g2c[E_MAX];       // src gene ids sorted by cell dst
__device__ int   g_csr_c2g[E_MAX];       // src cell ids sorted by gene dst
__device__ float g_feat_g[N_GENE * D];
__device__ float g_feat_c[N_CELL * D];
__device__ float g_agg_c[N_CELL * D];
__device__ float g_agg_g[N_GENE * D];
__device__ float g_sg[N_GENE];
__device__ float g_sc[N_CELL];

// ---------------- kernels ----------------

__global__ void k_zero() {
    int i = blockIdx.x * blockDim.x + threadIdx.x;
    if (i < N_GENE) { g_deg_gsrc[i] = 0; g_deg_gdst[i] = 0; g_cursor_g[i] = 0; }
    if (i < N_CELL) { g_deg_cdst[i] = 0; g_deg_csrc[i] = 0; g_cursor_c[i] = 0; }
}

__global__ void k_deg(const int* __restrict__ src, const int* __restrict__ dst,
                      int E, int rel) {
    int i = blockIdx.x * blockDim.x + threadIdx.x;
    if (i >= E) return;
    int s = src[i], d = dst[i];
    if (rel == 0) {
        atomicAdd(&g_deg_gsrc[s], 1);
        atomicAdd(&g_deg_cdst[d], 1);
    } else {
        atomicAdd(&g_deg_csrc[s], 1);
        atomicAdd(&g_deg_gdst[d], 1);
    }
}

// One block per array: blockIdx 0 -> cells (g2c dst), 1 -> genes (c2g dst).
__global__ void k_scan() {
    const int n = (blockIdx.x == 0) ? N_CELL : N_GENE;
    const int* deg = (blockIdx.x == 0) ? g_deg_cdst : g_deg_gdst;
    int* offs = (blockIdx.x == 0) ? g_offs_c : g_offs_g;

    __shared__ int svals[4800];
    __shared__ int spart[1024];
    int tid = threadIdx.x;

    for (int i = tid; i < n; i += 1024) svals[i] = deg[i];
    __syncthreads();

    int seg = (n + 1023) / 1024;
    int beg = tid * seg;
    int end = beg + seg; if (end > n) end = n;
    int s = 0;
    for (int i = beg; i < end; i++) { int v = svals[i]; svals[i] = s; s += v; }
    spart[tid] = s;
    __syncthreads();

    // inclusive Hillis-Steele scan of spart
    for (int off = 1; off < 1024; off <<= 1) {
        int v = (tid >= off) ? spart[tid - off] : 0;
        __syncthreads();
        spart[tid] += v;
        __syncthreads();
    }

    int base = (tid == 0) ? 0 : spart[tid - 1];
    for (int i = beg; i < end; i++) offs[i] = svals[i] + base;
    if (tid == 0) offs[n] = spart[1023];
}

__global__ void k_fill(const int* __restrict__ src, const int* __restrict__ dst,
                       int E, int rel) {
    int i = blockIdx.x * blockDim.x + threadIdx.x;
    if (i >= E) return;
    int s = src[i], d = dst[i];
    if (rel == 0) {
        int p = atomicAdd(&g_cursor_c[d], 1);
        g_csr_g2c[g_offs_c[d] + p] = s;
    } else {
        int p = atomicAdd(&g_cursor_g[d], 1);
        g_csr_c2g[g_offs_g[d] + p] = s;
    }
}

// feat = emb * deg_out^{-1/2} (clipped at 1)
__global__ void k_feat(const float* __restrict__ emb, int which) {
    const int* deg = (which == 0) ? g_deg_gsrc : g_deg_csrc;
    float* feat    = (which == 0) ? g_feat_g   : g_feat_c;
    int n          = (which == 0) ? N_GENE     : N_CELL;
    int i = blockIdx.x * blockDim.x + threadIdx.x;
    if (i >= n * D) return;
    int r = i >> 8;
    feat[i] = emb[i] * rsqrtf(fmaxf((float)deg[r], 1.0f));
}

// Aggregation: block = dst node, 256 threads = feature columns. Pure gather.
__global__ void k_agg(int rel) {
    const float* feat; const int* csr; const int* offs; const int* deg; float* outp;
    if (rel == 0) { feat = g_feat_g; csr = g_csr_g2c; offs = g_offs_c; deg = g_deg_cdst; outp = g_agg_c; }
    else          { feat = g_feat_c; csr = g_csr_c2g; offs = g_offs_g; deg = g_deg_gdst; outp = g_agg_g; }

    int b = blockIdx.x;
    int tid = threadIdx.x;
    int beg = offs[b], end = offs[b + 1];

    __shared__ int sidx[256];
    float acc = 0.0f;

    for (int base = beg; base < end; base += 256) {
        int m = end - base; if (m > 256) m = 256;
        __syncthreads();
        if (tid < m) sidx[tid] = csr[base + tid];
        __syncthreads();
        int j = 0;
        for (; j + 8 <= m; j += 8) {
            int i0 = sidx[j + 0], i1 = sidx[j + 1], i2 = sidx[j + 2], i3 = sidx[j + 3];
            int i4 = sidx[j + 4], i5 = sidx[j + 5], i6 = sidx[j + 6], i7 = sidx[j + 7];
            float f0 = feat[i0 * D + tid];
            float f1 = feat[i1 * D + tid];
            float f2 = feat[i2 * D + tid];
            float f3 = feat[i3 * D + tid];
            float f4 = feat[i4 * D + tid];
            float f5 = feat[i5 * D + tid];
            float f6 = feat[i6 * D + tid];
            float f7 = feat[i7 * D + tid];
            acc += f0; acc += f1; acc += f2; acc += f3;
            acc += f4; acc += f5; acc += f6; acc += f7;
        }
        for (; j < m; j++) acc += feat[sidx[j] * D + tid];
    }

    float nd = rsqrtf(fmaxf((float)deg[b], 1.0f));
    outp[b * D + tid] = acc * nd;
}

// O[gr] = relu(A[gr] @ W + bias), A from device scratch selected by rel.
__global__ void k_gemm(int rel, const float* __restrict__ W,
                       const float* __restrict__ bias, float* __restrict__ O) {
    const float* A = (rel == 0) ? g_agg_c : g_agg_g;
    int n          = (rel == 0) ? N_CELL  : N_GENE;

    __shared__ float sA[32][260];
    int row0 = blockIdx.x * 32;
    int tid = threadIdx.x;

    for (int i = tid; i < 32 * 256; i += 256) {
        int r = i >> 8, k = i & 255;
        int gr = row0 + r;
        sA[r][k] = (gr < n) ? A[gr * D + k] : 0.0f;
    }
    __syncthreads();

    float acc[32];
#pragma unroll
    for (int r = 0; r < 32; r++) acc[r] = 0.0f;

#pragma unroll 4
    for (int k = 0; k < 256; k++) {
        float w = W[k * D + tid];
#pragma unroll
        for (int r = 0; r < 32; r++) acc[r] = fmaf(sA[r][k], w, acc[r]);
    }

    float bv = bias[tid];
#pragma unroll
    for (int r = 0; r < 32; r++) {
        int gr = row0 + r;
        if (gr < n) O[gr * D + tid] = fmaxf(acc[r] + bv, 0.0f);
    }
}

// per-node scalar: sg[i] = dot(h[i,:], Wp[wpoff:wpoff+256])
__global__ void k_rowdot(const float* __restrict__ H, const float* __restrict__ Wp,
                         int which) {
    float* outv = (which == 0) ? g_sg : g_sc;
    int n       = (which == 0) ? N_GENE : N_CELL;
    int wpoff   = (which == 0) ? 0 : 256;

    int gidx = blockIdx.x * blockDim.x + threadIdx.x;
    int warp = gidx >> 5;
    int lane = gidx & 31;
    if (warp >= n) return;
    const float* row = H + warp * D;
    float s = 0.0f;
#pragma unroll
    for (int i = 0; i < 8; i++) s = fmaf(row[lane + 32 * i], Wp[wpoff + lane + 32 * i], s);
#pragma unroll
    for (int o = 16; o; o >>= 1) s += __shfl_xor_sync(0xFFFFFFFFu, s, o);
    if (lane == 0) outv[warp] = s;
}

__global__ void k_score(const int* __restrict__ dsrc, const int* __restrict__ ddst,
                        const float* __restrict__ bp, float* __restrict__ out, int E) {
    int i = blockIdx.x * blockDim.x + threadIdx.x;
    if (i >= E) return;
    out[i] = g_sg[dsrc[i]] + g_sc[ddst[i]] + bp[0];
}

// ---------------- launch ----------------
extern "C" void kernel_launch(void* const* d_in, const int* in_sizes, int n_in,
                              void* d_out, int out_size) {
    const float* gene_emb = (const float*)d_in[0];
    const float* cell_emb = (const float*)d_in[1];
    const float* W_g2c    = (const float*)d_in[2];
    const float* b_g2c    = (const float*)d_in[3];
    const float* W_c2g    = (const float*)d_in[4];
    const float* b_c2g    = (const float*)d_in[5];
    const float* Wp       = (const float*)d_in[6];
    const float* bp       = (const float*)d_in[7];
    const int* g2c_src    = (const int*)d_in[8];
    const int* g2c_dst    = (const int*)d_in[9];
    const int* c2g_src    = (const int*)d_in[10];
    const int* c2g_dst    = (const int*)d_in[11];
    const int* dec_src    = (const int*)d_in[12];
    const int* dec_dst    = (const int*)d_in[13];

    int E1 = in_sizes[8];
    int E2 = in_sizes[10];
    int E3 = in_sizes[12];

    float* out    = (float*)d_out;
    float* score  = out;                      // [E3]
    float* h_gene = out + E3;                 // [N_GENE, 256]
    float* h_cell = out + E3 + N_GENE * D;    // [N_CELL, 256]

    // 1) zero degree/cursor scratch
    k_zero<<<(N_GENE + 255) / 256, 256>>>();

    // 2) degrees for both relations
    k_deg<<<(E1 + 255) / 256, 256>>>(g2c_src, g2c_dst, E1, 0);
    k_deg<<<(E2 + 255) / 256, 256>>>(c2g_src, c2g_dst, E2, 1);

    // 3) prefix sums -> CSR offsets (block 0: cells, block 1: genes)
    k_scan<<<2, 1024>>>();

    // 4) CSR fill (counting sort by dst)
    k_fill<<<(E1 + 255) / 256, 256>>>(g2c_src, g2c_dst, E1, 0);
    k_fill<<<(E2 + 255) / 256, 256>>>(c2g_src, c2g_dst, E2, 1);

    // 5) src-side normalization
    k_feat<<<(N_GENE * D + 255) / 256, 256>>>(gene_emb, 0);
    k_feat<<<(N_CELL * D + 255) / 256, 256>>>(cell_emb, 1);

    // 6) aggregation (gather, atomic-free)
    k_agg<<<N_CELL, 256>>>(0);
    k_agg<<<N_GENE, 256>>>(1);

    // 7) GEMM + bias + relu, write straight into d_out
    k_gemm<<<(N_CELL + 31) / 32, 256>>>(0, W_g2c, b_g2c, h_cell);
    k_gemm<<<(N_GENE + 31) / 32, 256>>>(1, W_c2g, b_c2g, h_gene);

    // 8) predictor factorization: sg = h_gene@Wp[:256], sc = h_cell@Wp[256:]
    k_rowdot<<<(N_GENE * 32 + 255) / 256, 256>>>(h_gene, Wp, 0);
    k_rowdot<<<(N_CELL * 32 + 255) / 256, 256>>>(h_cell, Wp, 1);

    // 9) edge scores
    k_score<<<(E3 + 255) / 256, 256>>>(dec_src, dec_dst, bp, score, E3);
}

// round 2
// speedup vs baseline: 1.1394x; 1.1394x over previous
#include <cuda_runtime.h>
#include <cuda_bf16.h>

#define N_GENE 4762
#define N_CELL 847
#define D 256
#define E_MAX 200064

// ---------------- device scratch (no allocations allowed) ----------------
__device__ int   g_deg_gsrc[N_GENE];
__device__ int   g_deg_cdst[N_CELL];
__device__ int   g_deg_csrc[N_CELL];
__device__ int   g_deg_gdst[N_GENE];
__device__ float g_norm_gsrc[N_GENE];
__device__ float g_norm_cdst[N_CELL];
__device__ float g_norm_csrc[N_CELL];
__device__ float g_norm_gdst[N_GENE];
__device__ int   g_offs_c[N_CELL + 1];
__device__ int   g_offs_g[N_GENE + 1];
__device__ int   g_cursor_c[N_CELL];
__device__ int   g_cursor_g[N_GENE];
__device__ int   g_csr_g2c[E_MAX];
__device__ int   g_csr_c2g[E_MAX];
__device__ float g_agg_c[N_CELL * D];
__device__ float g_agg_g[N_GENE * D];
__device__ float g_sg[N_GENE];
__device__ float g_sc[N_CELL];

// ---------------- kernels ----------------

__global__ void k_zero() {
    int i = blockIdx.x * blockDim.x + threadIdx.x;
    if (i < N_GENE) { g_deg_gsrc[i] = 0; g_deg_gdst[i] = 0; g_cursor_g[i] = 0; }
    if (i < N_CELL) { g_deg_cdst[i] = 0; g_deg_csrc[i] = 0; g_cursor_c[i] = 0; }
}

// Both relations in one grid.
__global__ void k_deg(const int* __restrict__ s1, const int* __restrict__ d1, int E1,
                      const int* __restrict__ s2, const int* __restrict__ d2, int E2) {
    int i = blockIdx.x * blockDim.x + threadIdx.x;
    if (i < E1) {
        atomicAdd(&g_deg_gsrc[s1[i]], 1);
        atomicAdd(&g_deg_cdst[d1[i]], 1);
    } else if (i < E1 + E2) {
        int j = i - E1;
        atomicAdd(&g_deg_csrc[s2[j]], 1);
        atomicAdd(&g_deg_gdst[d2[j]], 1);
    }
}

// Two blocks: 0 -> cell offsets (g2c dst), 1 -> gene offsets (c2g dst).
// Two-level shfl scan + norm precompute.
__global__ void k_scan() {
    int b = blockIdx.x, tid = threadIdx.x;
    int n; const int* deg; int* offs;
    if (b == 0) { n = N_CELL; deg = g_deg_cdst; offs = g_offs_c; }
    else        { n = N_GENE; deg = g_deg_gdst; offs = g_offs_g; }

    int seg = (n + 1023) >> 10;   // <=5
    int beg = tid * seg;
    int vals[5];
    int run = 0;
#pragma unroll
    for (int i = 0; i < 5; i++) {
        if (i < seg) {
            int g = beg + i;
            int v = (g < n) ? deg[g] : 0;
            vals[i] = run; run += v;
        }
    }
    int lane = tid & 31, w = tid >> 5;
    int incl = run;
#pragma unroll
    for (int o = 1; o < 32; o <<= 1) {
        int v = __shfl_up_sync(0xffffffffu, incl, o);
        if (lane >= o) incl += v;
    }
    __shared__ int wsum[32];
    __shared__ int total;
    if (lane == 31) wsum[w] = incl;
    __syncthreads();
    if (w == 0) {
        int v = wsum[lane];
        int inc2 = v;
#pragma unroll
        for (int o = 1; o < 32; o <<= 1) {
            int t = __shfl_up_sync(0xffffffffu, inc2, o);
            if (lane >= o) inc2 += t;
        }
        wsum[lane] = inc2 - v;
        if (lane == 31) total = inc2;
    }
    __syncthreads();
    int base = wsum[w] + (incl - run);
#pragma unroll
    for (int i = 0; i < 5; i++) {
        if (i < seg) {
            int g = beg + i;
            if (g < n) offs[g] = base + vals[i];
        }
    }
    if (tid == 0) offs[n] = total;

    // norms (idle-thread work)
    if (b == 0) {
        for (int i = tid; i < N_CELL; i += 1024) {
            g_norm_cdst[i] = rsqrtf(fmaxf((float)g_deg_cdst[i], 1.0f));
            g_norm_csrc[i] = rsqrtf(fmaxf((float)g_deg_csrc[i], 1.0f));
        }
    } else {
        for (int i = tid; i < N_GENE; i += 1024) {
            g_norm_gdst[i] = rsqrtf(fmaxf((float)g_deg_gdst[i], 1.0f));
            g_norm_gsrc[i] = rsqrtf(fmaxf((float)g_deg_gsrc[i], 1.0f));
        }
    }
}

__global__ void k_fill(const int* __restrict__ s1, const int* __restrict__ d1, int E1,
                       const int* __restrict__ s2, const int* __restrict__ d2, int E2) {
    int i = blockIdx.x * blockDim.x + threadIdx.x;
    if (i < E1) {
        int s = s1[i], d = d1[i];
        int p = atomicAdd(&g_cursor_c[d], 1);
        g_csr_g2c[g_offs_c[d] + p] = s;
    } else if (i < E1 + E2) {
        int j = i - E1;
        int s = s2[j], d = d2[j];
        int p = atomicAdd(&g_cursor_g[d], 1);
        g_csr_c2g[g_offs_g[d] + p] = s;
    }
}

// Aggregation: block = dst node (cells then genes), 256 threads = columns.
// src-norm folded into the gather FMA.
__global__ void k_agg(const float* __restrict__ gene_emb,
                      const float* __restrict__ cell_emb) {
    int b = blockIdx.x, tid = threadIdx.x;
    const float* emb; const int* csr; const float* nsrc;
    float* outp; float nd; int beg, end;
    if (b < N_CELL) {
        emb = gene_emb; csr = g_csr_g2c; nsrc = g_norm_gsrc;
        beg = g_offs_c[b]; end = g_offs_c[b + 1];
        nd = g_norm_cdst[b]; outp = g_agg_c + b * D;
    } else {
        int r = b - N_CELL;
        emb = cell_emb; csr = g_csr_c2g; nsrc = g_norm_csrc;
        beg = g_offs_g[r]; end = g_offs_g[r + 1];
        nd = g_norm_gdst[r]; outp = g_agg_g + r * D;
    }

    __shared__ int   sidx[256];
    __shared__ float snrm[256];
    float acc = 0.0f;

    for (int base = beg; base < end; base += 256) {
        int m = end - base; if (m > 256) m = 256;
        __syncthreads();
        if (tid < m) {
            int idx = csr[base + tid];
            sidx[tid] = idx;
            snrm[tid] = nsrc[idx];
        }
        __syncthreads();
        int j = 0;
        for (; j + 8 <= m; j += 8) {
            float f0 = emb[sidx[j + 0] * D + tid];
            float f1 = emb[sidx[j + 1] * D + tid];
            float f2 = emb[sidx[j + 2] * D + tid];
            float f3 = emb[sidx[j + 3] * D + tid];
            float f4 = emb[sidx[j + 4] * D + tid];
            float f5 = emb[sidx[j + 5] * D + tid];
            float f6 = emb[sidx[j + 6] * D + tid];
            float f7 = emb[sidx[j + 7] * D + tid];
            acc = fmaf(f0, snrm[j + 0], acc);
            acc = fmaf(f1, snrm[j + 1], acc);
            acc = fmaf(f2, snrm[j + 2], acc);
            acc = fmaf(f3, snrm[j + 3], acc);
            acc = fmaf(f4, snrm[j + 4], acc);
            acc = fmaf(f5, snrm[j + 5], acc);
            acc = fmaf(f6, snrm[j + 6], acc);
            acc = fmaf(f7, snrm[j + 7], acc);
        }
        for (; j < m; j++) acc = fmaf(emb[sidx[j] * D + tid], snrm[j], acc);
    }

    outp[tid] = acc * nd;
}

// Combined GEMM (+bias+relu) with rowdot epilogue for the predictor.
// Blocks [0, CB): cells; [CB, CB+GB): genes.
__global__ void __launch_bounds__(256, 2)
k_gemm(const float* __restrict__ W_g2c, const float* __restrict__ b_g2c,
       const float* __restrict__ W_c2g, const float* __restrict__ b_c2g,
       const float* __restrict__ Wp,
       float* __restrict__ h_cell, float* __restrict__ h_gene) {
    const int CB = (N_CELL + 31) / 32;
    int blk = blockIdx.x, tid = threadIdx.x;

    const float* A; const float* W; const float* bias; float* O; float* sv;
    int n, row0, wpoff;
    if (blk < CB) {
        A = g_agg_c; W = W_g2c; bias = b_g2c; O = h_cell; sv = g_sc;
        n = N_CELL; row0 = blk * 32; wpoff = 256;
    } else {
        A = g_agg_g; W = W_c2g; bias = b_c2g; O = h_gene; sv = g_sg;
        n = N_GENE; row0 = (blk - CB) * 32; wpoff = 0;
    }

    __shared__ float sA[32][260];
    for (int i = tid; i < 32 * 256; i += 256) {
        int r = i >> 8, k = i & 255;
        int gr = row0 + r;
        sA[r][k] = (gr < n) ? A[gr * D + k] : 0.0f;
    }
    __syncthreads();

    float acc[32];
#pragma unroll
    for (int r = 0; r < 32; r++) acc[r] = 0.0f;

#pragma unroll 4
    for (int k = 0; k < 256; k++) {
        float w = W[k * D + tid];
#pragma unroll
        for (int r = 0; r < 32; r++) acc[r] = fmaf(sA[r][k], w, acc[r]);
    }

    float bv = bias[tid];
    float wpv = Wp[wpoff + tid];
    int lane = tid & 31, wrp = tid >> 5;
    __shared__ float sred[32][9];

#pragma unroll
    for (int r = 0; r < 32; r++) {
        int gr = row0 + r;
        float h = fmaxf(acc[r] + bv, 0.0f);
        if (gr < n) O[gr * D + tid] = h;
        float p = (gr < n) ? h * wpv : 0.0f;
#pragma unroll
        for (int o = 16; o; o >>= 1) p += __shfl_xor_sync(0xffffffffu, p, o);
        if (lane == 0) sred[r][wrp] = p;
    }
    __syncthreads();
    if (tid < 32) {
        float s = 0.0f;
#pragma unroll
        for (int w8 = 0; w8 < 8; w8++) s += sred[tid][w8];
        int gr = row0 + tid;
        if (gr < n) sv[gr] = s;
    }
}

__global__ void k_score(const int* __restrict__ dsrc, const int* __restrict__ ddst,
                        const float* __restrict__ bp, float* __restrict__ out, int E) {
    int i = blockIdx.x * blockDim.x + threadIdx.x;
    if (i >= E) return;
    out[i] = g_sg[dsrc[i]] + g_sc[ddst[i]] + bp[0];
}

// ---------------- launch ----------------
extern "C" void kernel_launch(void* const* d_in, const int* in_sizes, int n_in,
                              void* d_out, int out_size) {
    const float* gene_emb = (const float*)d_in[0];
    const float* cell_emb = (const float*)d_in[1];
    const float* W_g2c    = (const float*)d_in[2];
    const float* b_g2c    = (const float*)d_in[3];
    const float* W_c2g    = (const float*)d_in[4];
    const float* b_c2g    = (const float*)d_in[5];
    const float* Wp       = (const float*)d_in[6];
    const float* bp       = (const float*)d_in[7];
    const int* g2c_src    = (const int*)d_in[8];
    const int* g2c_dst    = (const int*)d_in[9];
    const int* c2g_src    = (const int*)d_in[10];
    const int* c2g_dst    = (const int*)d_in[11];
    const int* dec_src    = (const int*)d_in[12];
    const int* dec_dst    = (const int*)d_in[13];

    int E1 = in_sizes[8];
    int E2 = in_sizes[10];
    int E3 = in_sizes[12];

    float* out    = (float*)d_out;
    float* score  = out;
    float* h_gene = out + E3;
    float* h_cell = out + E3 + N_GENE * D;

    k_zero<<<(N_GENE + 255) / 256, 256>>>();
    k_deg<<<(E1 + E2 + 255) / 256, 256>>>(g2c_src, g2c_dst, E1, c2g_src, c2g_dst, E2);
    k_scan<<<2, 1024>>>();
    k_fill<<<(E1 + E2 + 255) / 256, 256>>>(g2c_src, g2c_dst, E1, c2g_src, c2g_dst, E2);
    k_agg<<<N_CELL + N_GENE, 256>>>(gene_emb, cell_emb);

    const int CB = (N_CELL + 31) / 32;
    const int GB = (N_GENE + 31) / 32;
    k_gemm<<<CB + GB, 256>>>(W_g2c, b_g2c, W_c2g, b_c2g, Wp, h_cell, h_gene);

    k_score<<<(E3 + 255) / 256, 256>>>(dec_src, dec_dst, bp, score, E3);
}